// round 12
// baseline (speedup 1.0000x reference)
#include <cuda_runtime.h>
#include <cuda_bf16.h>
#include <math.h>
#include <cstdint>

#define N_CELLS 10000
#define P_GENES 8000
#define L_FAC   100
#define LAM_D   0.01
#define DELTA_F 0.001f

#define GRID_X  63                    // column panels
#define GRID_Y1 79                    // recon row panels
#define NT      7                     // tiles per block
#define NGRP    9                     // column groups (9*7 = 63)
#define N_PADR  (GRID_Y1 * 128)       // 10112
#define P_PADR  (GRID_X * 128)        // 8064
#define NPART1  (GRID_Y1 * NGRP)      // 711
#define NPART2  (GRID_X * NGRP)       // 567

// fragment-major panel: 8 mblocks x 7 kblocks x 128 u32
#define PANEL_U32   (8 * 7 * 128)     // 7168 u32 = 28672 B
#define PANEL_UINT4 (PANEL_U32 / 4)   // 1792
#define PANEL_BYTES (PANEL_U32 * 4)
#define BITS_BYTES  2048              // 128 rows x 16 bytes of adj bits
#define SMEM_RECON  (3 * PANEL_BYTES)                       // 86016
#define SMEM_MAT    (PANEL_BYTES + 2 * (PANEL_BYTES + BITS_BYTES))  // 90112

// adj bitmask: 1024-byte padded row stride (256 u32 per row)
#define ABITS_ROWU32 256

// ---------------- device scratch (zero-initialized; pads stay 0) ---------
__device__ __align__(16) unsigned g_a_fr  [(N_PADR / 128) * PANEL_U32];  // A-layout
__device__ __align__(16) unsigned g_B_fr  [(P_PADR / 128) * PANEL_U32];  // A-layout
__device__ __align__(16) unsigned g_th_fr [(P_PADR / 128) * PANEL_U32];  // B-layout
__device__ __align__(16) unsigned g_thp_fr[(P_PADR / 128) * PANEL_U32];  // B-layout
__device__ __align__(16) unsigned g_adjbits[P_PADR * ABITS_ROWU32];      // 8.25 MB
__device__ float  g_et[L_FAC * L_FAC];
__device__ double g_part1[1024];
__device__ double g_part2[1024];

// ---------------- streams/events (created at load; capture-legal) --------
static cudaStream_t g_s2, g_s3;
static cudaEvent_t  g_evStart, g_evTh, g_evA, g_evM, g_evP;
static const bool g_init_done = [](){
    cudaStreamCreateWithFlags(&g_s2, cudaStreamNonBlocking);
    cudaStreamCreateWithFlags(&g_s3, cudaStreamNonBlocking);
    cudaEventCreateWithFlags(&g_evStart, cudaEventDisableTiming);
    cudaEventCreateWithFlags(&g_evTh,    cudaEventDisableTiming);
    cudaEventCreateWithFlags(&g_evA,     cudaEventDisableTiming);
    cudaEventCreateWithFlags(&g_evM,     cudaEventDisableTiming);
    cudaEventCreateWithFlags(&g_evP,     cudaEventDisableTiming);
    return true;
}();

__device__ __forceinline__ float sigmoidf_(float x) {
    return 1.0f / (1.0f + expf(-x));
}
__device__ __forceinline__ unsigned pack_bf2(float a, float b) {
    __nv_bfloat162 h = __floats2bfloat162_rn(a, b);
    return *reinterpret_cast<unsigned*>(&h);
}
__device__ __forceinline__ void pref_l2(const void* p) {
    asm volatile("prefetch.global.L2 [%0];" :: "l"(p));
}
__device__ __forceinline__ void cp16(void* sp, const void* gp) {
    unsigned s = (unsigned)__cvta_generic_to_shared(sp);
    asm volatile("cp.async.cg.shared.global [%0], [%1], 16;" :: "r"(s), "l"(gp));
}
#define CP_COMMIT() asm volatile("cp.async.commit_group;" ::: "memory")
#define CP_WAIT0()  asm volatile("cp.async.wait_group 0;" ::: "memory")

// A-layout address (u32 index), k even pair base
__device__ __forceinline__ int a_off(int row, int kk) {
    int p  = row >> 7, rm = row & 127;
    int m8 = rm >> 4,  ri = rm & 15;
    int kb = kk >> 4;
    int lane = (ri & 7) * 4 + ((kk & 7) >> 1);
    int reg  = (ri >> 3) + 2 * ((kk & 15) >> 3);
    return ((p * 8 + m8) * 7 + kb) * 128 + lane * 4 + reg;
}
// B-layout address (u32 index), k even pair base
__device__ __forceinline__ int b_off(int n, int kk) {
    int q  = n >> 7, nm = n & 127;
    int np4 = nm >> 4, ni = nm & 15, sub = ni >> 3;
    int kb = kk >> 4;
    int lane = (ni & 7) * 4 + ((kk & 7) >> 1);
    int reg  = ((kk & 15) >> 3) + 2 * sub;
    return ((q * 8 + np4) * 7 + kb) * 128 + lane * 4 + reg;
}

// ---------------- pack adj (binary float) -> bitmask ---------------------
__global__ void pack_adj_kernel(const float* __restrict__ adj) {
    int idx = blockIdx.x * blockDim.x + threadIdx.x;   // 8000 * 250
    if (idx >= P_GENES * 250) return;
    int row = idx / 250, cb = idx % 250;
    const float4* p = (const float4*)(adj + (size_t)row * P_GENES + cb * 32);
    unsigned w = 0;
    #pragma unroll
    for (int q = 0; q < 8; q++) {
        float4 v = __ldcs(p + q);
        int base = q * 4;
        w |= (v.x > 0.5f ? 1u : 0u) << (base + 0);
        w |= (v.y > 0.5f ? 1u : 0u) << (base + 1);
        w |= (v.z > 0.5f ? 1u : 0u) << (base + 2);
        w |= (v.w > 0.5f ? 1u : 0u) << (base + 3);
    }
    g_adjbits[row * ABITS_ROWU32 + cb] = w;
}

// ---------------- et ----------------
__global__ void et_kernel(const float* __restrict__ eta) {
    int idx = blockIdx.x * blockDim.x + threadIdx.x;
    if (idx >= L_FAC * L_FAC) return;
    int i = idx / L_FAC, j = idx % L_FAC;
    g_et[idx] = 0.5f * (sigmoidf_(eta[i * L_FAC + j]) + sigmoidf_(eta[j * L_FAC + i]));
}

// ---------------- a = exp(alpha) -> fragment-major A-layout --------------
__global__ void expa_kernel(const float* __restrict__ alpha) {
    int idx = blockIdx.x * blockDim.x + threadIdx.x;
    if (idx >= N_PADR * 56) return;
    int row = idx / 56, kk = (idx % 56) * 2;
    float e0 = 0.0f, e1 = 0.0f;
    if (row < N_CELLS) {
        if (kk < L_FAC)     e0 = expf(alpha[row * L_FAC + kk]);
        if (kk + 1 < L_FAC) e1 = expf(alpha[row * L_FAC + kk + 1]);
    }
    g_a_fr[a_off(row, kk)] = pack_bf2(e0, e1);
}

// ---------------- per-gene: softmax, theta_, B = th@et -------------------
__global__ void __launch_bounds__(256)
theta_kernel(const float* __restrict__ theta, const float* __restrict__ gs) {
    __shared__ float et_s[L_FAC * L_FAC];
    __shared__ float th_s[16][L_FAC];
    __shared__ float gsc_s[16];

    int tid = threadIdx.x;
    for (int i = tid; i < L_FAC * L_FAC; i += 256) et_s[i] = g_et[i];

    int warp = tid >> 5, lane = tid & 31;
    int rowl = warp * 2 + (lane >> 4);
    int l16  = lane & 15;
    int gene = blockIdx.x * 16 + rowl;

    float v[7];
    float mx = -1e30f;
    #pragma unroll
    for (int j = 0; j < 7; j++) {
        int idx = l16 + 16 * j;
        v[j] = (idx < L_FAC) ? theta[gene * L_FAC + idx] : -1e30f;
        mx = fmaxf(mx, v[j]);
    }
    #pragma unroll
    for (int off = 8; off > 0; off >>= 1)
        mx = fmaxf(mx, __shfl_xor_sync(0xffffffff, mx, off, 16));
    float sum = 0.0f;
    #pragma unroll
    for (int j = 0; j < 7; j++) {
        int idx = l16 + 16 * j;
        v[j] = (idx < L_FAC) ? expf(v[j] - mx) : 0.0f;
        sum += v[j];
    }
    #pragma unroll
    for (int off = 8; off > 0; off >>= 1)
        sum += __shfl_xor_sync(0xffffffff, sum, off, 16);
    float inv = 1.0f / sum;

    #pragma unroll
    for (int j = 0; j < 7; j++) {
        int idx = l16 + 16 * j;
        if (idx < L_FAC) th_s[rowl][idx] = v[j] * inv;
    }
    if (l16 == 0) gsc_s[rowl] = sigmoidf_(gs[gene]) + DELTA_F;
    __syncthreads();

    for (int idx = tid; idx < 16 * 56; idx += 256) {
        int r = idx / 56, kk = (idx % 56) * 2;
        int n = blockIdx.x * 16 + r;
        float t0 = (kk < L_FAC) ? th_s[r][kk] : 0.0f;
        float t1 = (kk + 1 < L_FAC) ? th_s[r][kk + 1] : 0.0f;
        float g = gsc_s[r];
        int off = b_off(n, kk);
        g_th_fr [off] = pack_bf2(t0, t1);
        g_thp_fr[off] = pack_bf2(t0 * g, t1 * g);
    }

    for (int idx = tid; idx < 16 * 56; idx += 256) {
        int r = idx / 56, kk = (idx % 56) * 2;
        int row = blockIdx.x * 16 + r;
        float a0 = 0.0f, a1 = 0.0f;
        if (kk < L_FAC) {
            #pragma unroll 4
            for (int m = 0; m < L_FAC; m++) {
                float t = th_s[r][m];
                a0 = fmaf(t, et_s[m * L_FAC + kk], a0);
                if (kk + 1 < L_FAC) a1 = fmaf(t, et_s[m * L_FAC + kk + 1], a1);
            }
        }
        g_B_fr[a_off(row, kk)] = pack_bf2(a0, a1);
    }
}

// =====================================================================
// multi-tile GEMM machinery
// =====================================================================
__device__ __forceinline__ void mma16816(float c[4], const unsigned a[4],
                                         unsigned b0, unsigned b1) {
    asm volatile(
        "mma.sync.aligned.m16n8k16.row.col.f32.bf16.bf16.f32 "
        "{%0,%1,%2,%3}, {%4,%5,%6,%7}, {%8,%9}, {%0,%1,%2,%3};"
        : "+f"(c[0]), "+f"(c[1]), "+f"(c[2]), "+f"(c[3])
        : "r"(a[0]), "r"(a[1]), "r"(a[2]), "r"(a[3]), "r"(b0), "r"(b1));
}

__device__ __forceinline__ void stage_panel(char* dst, const uint4* src, int tid) {
    #pragma unroll
    for (int j = 0; j < 4; j++) {
        int i = tid + j * 512;
        if (i < PANEL_UINT4) cp16(dst + i * 16, src + i);
    }
}

// stage 128 rows x 16 bytes of adj bits for (rowBase, colPanel)
__device__ __forceinline__ void stage_bits(char* dst, int rowBase, int colPanel, int tid) {
    if (tid < 128) {
        const char* src = (const char*)g_adjbits
                        + (size_t)(rowBase + tid) * (ABITS_ROWU32 * 4) + colPanel * 16;
        cp16(dst + tid * 16, src);
    }
}

__device__ __forceinline__ void tile_mma(const char* As, const char* Bs,
                                         float acc[2][4][4], int lane, int wm, int wn) {
    int laneOff = lane * 16;
    #pragma unroll
    for (int mi = 0; mi < 2; mi++)
        #pragma unroll
        for (int nj = 0; nj < 4; nj++)
            #pragma unroll
            for (int q = 0; q < 4; q++) acc[mi][nj][q] = 0.0f;
    #pragma unroll
    for (int ks = 0; ks < 7; ks++) {
        uint4 vA0 = *(const uint4*)(As + ((2 * wm + 0) * 7 + ks) * 512 + laneOff);
        uint4 vA1 = *(const uint4*)(As + ((2 * wm + 1) * 7 + ks) * 512 + laneOff);
        uint4 vB0 = *(const uint4*)(Bs + ((2 * wn + 0) * 7 + ks) * 512 + laneOff);
        uint4 vB1 = *(const uint4*)(Bs + ((2 * wn + 1) * 7 + ks) * 512 + laneOff);
        unsigned a0[4] = {vA0.x, vA0.y, vA0.z, vA0.w};
        unsigned a1[4] = {vA1.x, vA1.y, vA1.z, vA1.w};
        mma16816(acc[0][0], a0, vB0.x, vB0.y);
        mma16816(acc[0][1], a0, vB0.z, vB0.w);
        mma16816(acc[0][2], a0, vB1.x, vB1.y);
        mma16816(acc[0][3], a0, vB1.z, vB1.w);
        mma16816(acc[1][0], a1, vB0.x, vB0.y);
        mma16816(acc[1][1], a1, vB0.z, vB0.w);
        mma16816(acc[1][2], a1, vB1.x, vB1.y);
        mma16816(acc[1][3], a1, vB1.z, vB1.w);
    }
}

__device__ __forceinline__ double block_reduce512(float lsum, int tid) {
    __shared__ float red[16];
    #pragma unroll
    for (int off = 16; off > 0; off >>= 1)
        lsum += __shfl_xor_sync(0xffffffff, lsum, off);
    if ((tid & 31) == 0) red[tid >> 5] = lsum;
    __syncthreads();
    double t = 0.0;
    if (tid == 0) {
        #pragma unroll
        for (int w = 0; w < 16; w++) t += (double)red[w];
    }
    return t;
}

// ---- recon: 7 tiles per block; barrier BEFORE epilogue (skew-free) ----
__global__ void __launch_bounds__(512, 2)
recon_kernel(const float* __restrict__ X) {
    extern __shared__ char dsm[];
    char* As  = dsm;
    char* Bs0 = dsm + PANEL_BYTES;
    char* Bs1 = dsm + 2 * PANEL_BYTES;

    int tid = threadIdx.x;
    int lane = tid & 31, warp = tid >> 5;
    int wm = warp >> 2, wn = warp & 3;
    int rq = lane >> 2, kp = (lane & 3) << 1;
    int rowBase = blockIdx.y * 128;
    int col0 = blockIdx.x * NT;

    stage_panel(As,  ((const uint4*)g_a_fr)   + (size_t)blockIdx.y * PANEL_UINT4, tid);
    stage_panel(Bs0, ((const uint4*)g_thp_fr) + (size_t)col0 * PANEL_UINT4, tid);
    CP_COMMIT();
    CP_WAIT0();
    __syncthreads();

    float tot = 0.0f;
    #pragma unroll
    for (int t = 0; t < NT; t++) {
        char* Bcur = (t & 1) ? Bs1 : Bs0;
        char* Bnxt = (t & 1) ? Bs0 : Bs1;
        if (t + 1 < NT) {
            stage_panel(Bnxt, ((const uint4*)g_thp_fr) + (size_t)(col0 + t + 1) * PANEL_UINT4, tid);
            CP_COMMIT();
        }
        int colBase = (col0 + t) * 128;

        // prefetch this tile's epilogue X rows into L2 (quad leaders)
        if ((lane & 3) == 0) {
            #pragma unroll
            for (int mi = 0; mi < 2; mi++)
                #pragma unroll
                for (int half = 0; half < 2; half++) {
                    int r = rowBase + wm * 32 + mi * 16 + rq + half * 8;
                    if (r < N_CELLS) {
                        #pragma unroll
                        for (int nj = 0; nj < 4; nj++) {
                            int c = colBase + wn * 32 + nj * 8;
                            if (c < P_GENES) pref_l2(X + (size_t)r * P_GENES + c);
                        }
                    }
                }
        }

        float acc[2][4][4];
        tile_mma(As, Bcur, acc, lane, wm, wn);

        // barrier BEFORE epilogue: gates only on MMA done + cp.async arrival.
        // After this point Bcur(t) is dead, so stage(t+2) may overwrite it
        // while slow warps are still in this tile's epilogue.
        if (t + 1 < NT) {
            CP_WAIT0();
            __syncthreads();
        }

        float ls0 = 0.0f, ls1 = 0.0f;
        #pragma unroll
        for (int mi = 0; mi < 2; mi++) {
            #pragma unroll
            for (int nj = 0; nj < 4; nj++) {
                int r = rowBase + wm * 32 + mi * 16 + rq;
                int c = colBase + wn * 32 + nj * 8 + kp;
                if (c < P_GENES) {
                    if (r < N_CELLS) {
                        float2 x = *(const float2*)(X + (size_t)r * P_GENES + c);
                        float rec = acc[mi][nj][0];
                        ls0 += ((x.x > 0.0f) ? x.x * __logf(rec) : 0.0f) - rec;
                        rec = acc[mi][nj][1];
                        ls1 += ((x.y > 0.0f) ? x.y * __logf(rec) : 0.0f) - rec;
                    }
                    if (r + 8 < N_CELLS) {
                        float2 x = *(const float2*)(X + (size_t)(r + 8) * P_GENES + c);
                        float rec = acc[mi][nj][2];
                        ls0 += ((x.x > 0.0f) ? x.x * __logf(rec) : 0.0f) - rec;
                        rec = acc[mi][nj][3];
                        ls1 += ((x.y > 0.0f) ? x.y * __logf(rec) : 0.0f) - rec;
                    }
                }
            }
        }
        tot += ls0 + ls1;
    }
    double r = block_reduce512(tot, tid);
    if (tid == 0) g_part1[blockIdx.y * NGRP + blockIdx.x] = r;
}

// ---- mat: 7 tiles per block, adj bits; barrier BEFORE epilogue ----
__global__ void __launch_bounds__(512, 2)
mat_kernel(const float* __restrict__ kappa,
           const float* __restrict__ rho) {
    extern __shared__ char dsm[];
    char* As    = dsm;
    char* Bs0   = dsm + PANEL_BYTES;
    char* bits0 = Bs0 + PANEL_BYTES;
    char* Bs1   = bits0 + BITS_BYTES;
    char* bits1 = Bs1 + PANEL_BYTES;

    int tid = threadIdx.x;
    int lane = tid & 31, warp = tid >> 5;
    int wm = warp >> 2, wn = warp & 3;
    int rq = lane >> 2, kp = (lane & 3) << 1;
    int rowBase = blockIdx.y * 128;
    int col0 = blockIdx.x * NT;

    stage_panel(As,  ((const uint4*)g_B_fr)  + (size_t)blockIdx.y * PANEL_UINT4, tid);
    stage_panel(Bs0, ((const uint4*)g_th_fr) + (size_t)col0 * PANEL_UINT4, tid);
    stage_bits(bits0, rowBase, col0, tid);
    CP_COMMIT();
    CP_WAIT0();
    __syncthreads();

    float sk = sigmoidf_(kappa[0]);
    float sr = sigmoidf_(rho[0]);
    float Af = (1.0f - sr) * (1.0f - sk);
    float C2 = (1.0f - sr) * sk;
    float C3 = Af + sr;

    float tot = 0.0f;
    #pragma unroll
    for (int t = 0; t < NT; t++) {
        char* Bcur = (t & 1) ? Bs1 : Bs0;
        char* Bnxt = (t & 1) ? Bs0 : Bs1;
        char* bcur = (t & 1) ? bits1 : bits0;
        char* bnxt = (t & 1) ? bits0 : bits1;
        if (t + 1 < NT) {
            stage_panel(Bnxt, ((const uint4*)g_th_fr) + (size_t)(col0 + t + 1) * PANEL_UINT4, tid);
            stage_bits(bnxt, rowBase, col0 + t + 1, tid);
            CP_COMMIT();
        }
        int colBase = (col0 + t) * 128;

        float acc[2][4][4];
        tile_mma(As, Bcur, acc, lane, wm, wn);

        // read adj bits for this tile BEFORE the barrier (bcur(t) buffer is
        // overwritten by stage(t+2) once warps pass the next barrier)
        unsigned wb[2][2];
        #pragma unroll
        for (int mi = 0; mi < 2; mi++)
            #pragma unroll
            for (int half = 0; half < 2; half++) {
                int lr = wm * 32 + mi * 16 + rq + half * 8;
                wb[mi][half] = *(const unsigned*)(bcur + lr * 16 + wn * 4);
            }

        if (t + 1 < NT) {
            CP_WAIT0();
            __syncthreads();
        }

        float ls0 = 0.0f, ls1 = 0.0f;
        #pragma unroll
        for (int mi = 0; mi < 2; mi++) {
            #pragma unroll
            for (int nj = 0; nj < 4; nj++) {
                int r0 = rowBase + wm * 32 + mi * 16 + rq;
                int c  = colBase + wn * 32 + nj * 8 + kp;
                if (c < P_GENES) {
                    #pragma unroll
                    for (int half = 0; half < 2; half++) {
                        int r = r0 + half * 8;
                        if (r < P_GENES) {
                            unsigned w = wb[mi][half] >> (nj * 8 + kp);
                            float m0 = acc[mi][nj][half * 2 + 0];
                            float m1 = acc[mi][nj][half * 2 + 1];
                            float arg0 = (w & 1u) ? fmaf(Af, m0, C2) : fmaf(-Af, m0, C3);
                            float arg1 = (w & 2u) ? fmaf(Af, m1, C2) : fmaf(-Af, m1, C3);
                            if (r != c)     ls0 += __logf(arg0);
                            if (r != c + 1) ls1 += __logf(arg1);
                        }
                    }
                }
            }
        }
        tot += ls0 + ls1;
    }
    double r = block_reduce512(tot, tid);
    if (tid == 0) g_part2[blockIdx.y * NGRP + blockIdx.x] = r;
}

// ---------------- final reduction ----------------
__global__ void __launch_bounds__(256)
fin_kernel(float* out) {
    int tid = threadIdx.x;
    double s1 = 0.0, s2 = 0.0;
    for (int i = tid; i < NPART1; i += 256) s1 += g_part1[i];
    for (int i = tid; i < NPART2; i += 256) s2 += g_part2[i];
    #pragma unroll
    for (int off = 16; off > 0; off >>= 1) {
        s1 += __shfl_xor_sync(0xffffffff, s1, off);
        s2 += __shfl_xor_sync(0xffffffff, s2, off);
    }
    __shared__ double r1[8], r2[8];
    if ((tid & 31) == 0) { r1[tid >> 5] = s1; r2[tid >> 5] = s2; }
    __syncthreads();
    if (tid == 0) {
        double t1 = 0.0, t2 = 0.0;
        #pragma unroll
        for (int w = 0; w < 8; w++) { t1 += r1[w]; t2 += r2[w]; }
        out[0] = (float)(-(LAM_D * t1 + t2));
    }
}

// ---------------- launch ----------------
extern "C" void kernel_launch(void* const* d_in, const int* in_sizes, int n_in,
                              void* d_out, int out_size) {
    const float* X     = (const float*)d_in[0];
    const float* adj   = (const float*)d_in[1];
    // d_in[2] adj_1m, d_in[3] weights: derivable from binary adj, unused
    const float* theta = (const float*)d_in[4];
    const float* alpha = (const float*)d_in[5];
    const float* eta   = (const float*)d_in[6];
    const float* gs    = (const float*)d_in[7];
    const float* kappa = (const float*)d_in[8];
    const float* rho   = (const float*)d_in[9];
    float* out = (float*)d_out;

    cudaFuncSetAttribute(recon_kernel, cudaFuncAttributeMaxDynamicSharedMemorySize, SMEM_RECON);
    cudaFuncSetAttribute(mat_kernel,   cudaFuncAttributeMaxDynamicSharedMemorySize, SMEM_MAT);

    // fork s2, s3 off capture stream
    cudaEventRecord(g_evStart, 0);
    cudaStreamWaitEvent(g_s2, g_evStart, 0);
    cudaStreamWaitEvent(g_s3, g_evStart, 0);

    // s3: pack adj -> bitmask (overlaps everything)
    pack_adj_kernel<<<(P_GENES * 250 + 255) / 256, 256, 0, g_s3>>>(adj);
    cudaEventRecord(g_evP, g_s3);

    // s2: a = exp(alpha)
    expa_kernel<<<(N_PADR * 56 + 255) / 256, 256, 0, g_s2>>>(alpha);
    cudaEventRecord(g_evA, g_s2);

    // s0: et -> theta
    et_kernel<<<(L_FAC * L_FAC + 255) / 256, 256>>>(eta);
    theta_kernel<<<P_GENES / 16, 256>>>(theta, gs);
    cudaEventRecord(g_evTh, 0);

    // s2: mat (needs theta outputs + adj bits)
    cudaStreamWaitEvent(g_s2, g_evTh, 0);
    cudaStreamWaitEvent(g_s2, g_evP, 0);
    dim3 gMat(NGRP, GRID_X);
    mat_kernel<<<gMat, 512, SMEM_MAT, g_s2>>>(kappa, rho);
    cudaEventRecord(g_evM, g_s2);

    // s0: recon (needs g_a and theta outputs)
    cudaStreamWaitEvent(0, g_evA, 0);
    dim3 gRecon(NGRP, GRID_Y1);
    recon_kernel<<<gRecon, 512, SMEM_RECON>>>(X);

    // join
    cudaStreamWaitEvent(0, g_evM, 0);
    fin_kernel<<<1, 256>>>(out);
}

// round 14
// speedup vs baseline: 1.4479x; 1.4479x over previous
#include <cuda_runtime.h>
#include <cuda_bf16.h>
#include <math.h>
#include <cstdint>

#define N_CELLS 10000
#define P_GENES 8000
#define L_FAC   100
#define LAM_D   0.01
#define DELTA_F 0.001f

#define GRID_X  63                    // column panels
#define GRID_Y1 79                    // recon row panels
#define NT      7                     // tiles per block
#define NGRP    9                     // column groups (9*7 = 63)
#define N_PADR  (GRID_Y1 * 128)       // 10112
#define P_PADR  (GRID_X * 128)        // 8064
#define NPART1  (GRID_Y1 * NGRP)      // 711
#define NPART2  (GRID_X * NGRP)       // 567

// fragment-major panel: 8 mblocks x 7 kblocks x 128 u32
#define PANEL_U32   (8 * 7 * 128)     // 7168 u32 = 28672 B
#define PANEL_UINT4 (PANEL_U32 / 4)   // 1792
#define PANEL_BYTES (PANEL_U32 * 4)
#define BITS_BYTES  2048              // 128 rows x 16 bytes of adj bits
#define SMEM_RECON  (3 * PANEL_BYTES)                       // 86016
#define SMEM_MAT    (PANEL_BYTES + 2 * (PANEL_BYTES + BITS_BYTES))  // 90112

// adj bitmask: 1024-byte padded row stride (256 u32 per row)
#define ABITS_ROWU32 256

// ---------------- device scratch (zero-initialized; pads stay 0) ---------
__device__ __align__(16) unsigned g_a_fr  [(N_PADR / 128) * PANEL_U32];  // A-layout
__device__ __align__(16) unsigned g_B_fr  [(P_PADR / 128) * PANEL_U32];  // A-layout
__device__ __align__(16) unsigned g_th_fr [(P_PADR / 128) * PANEL_U32];  // B-layout
__device__ __align__(16) unsigned g_thp_fr[(P_PADR / 128) * PANEL_U32];  // B-layout
__device__ __align__(16) unsigned g_adjbits[P_PADR * ABITS_ROWU32];      // 8.25 MB
__device__ float  g_et[L_FAC * L_FAC];
__device__ double g_part1[1024];
__device__ double g_part2[1024];

// ---------------- streams/events (created at load; capture-legal) --------
static cudaStream_t g_s2, g_s3;
static cudaEvent_t  g_evStart, g_evTh, g_evA, g_evM, g_evP;
static const bool g_init_done = [](){
    cudaStreamCreateWithFlags(&g_s2, cudaStreamNonBlocking);
    cudaStreamCreateWithFlags(&g_s3, cudaStreamNonBlocking);
    cudaEventCreateWithFlags(&g_evStart, cudaEventDisableTiming);
    cudaEventCreateWithFlags(&g_evTh,    cudaEventDisableTiming);
    cudaEventCreateWithFlags(&g_evA,     cudaEventDisableTiming);
    cudaEventCreateWithFlags(&g_evM,     cudaEventDisableTiming);
    cudaEventCreateWithFlags(&g_evP,     cudaEventDisableTiming);
    return true;
}();

__device__ __forceinline__ float sigmoidf_(float x) {
    return 1.0f / (1.0f + expf(-x));
}
__device__ __forceinline__ unsigned pack_bf2(float a, float b) {
    __nv_bfloat162 h = __floats2bfloat162_rn(a, b);
    return *reinterpret_cast<unsigned*>(&h);
}
__device__ __forceinline__ void pref_l2(const void* p) {
    asm volatile("prefetch.global.L2 [%0];" :: "l"(p));
}
__device__ __forceinline__ void cp16(void* sp, const void* gp) {
    unsigned s = (unsigned)__cvta_generic_to_shared(sp);
    asm volatile("cp.async.cg.shared.global [%0], [%1], 16;" :: "r"(s), "l"(gp));
}
#define CP_COMMIT() asm volatile("cp.async.commit_group;" ::: "memory")
#define CP_WAIT0()  asm volatile("cp.async.wait_group 0;" ::: "memory")

// A-layout address (u32 index), k even pair base
__device__ __forceinline__ int a_off(int row, int kk) {
    int p  = row >> 7, rm = row & 127;
    int m8 = rm >> 4,  ri = rm & 15;
    int kb = kk >> 4;
    int lane = (ri & 7) * 4 + ((kk & 7) >> 1);
    int reg  = (ri >> 3) + 2 * ((kk & 15) >> 3);
    return ((p * 8 + m8) * 7 + kb) * 128 + lane * 4 + reg;
}
// B-layout address (u32 index), k even pair base
__device__ __forceinline__ int b_off(int n, int kk) {
    int q  = n >> 7, nm = n & 127;
    int np4 = nm >> 4, ni = nm & 15, sub = ni >> 3;
    int kb = kk >> 4;
    int lane = (ni & 7) * 4 + ((kk & 7) >> 1);
    int reg  = ((kk & 15) >> 3) + 2 * sub;
    return ((q * 8 + np4) * 7 + kb) * 128 + lane * 4 + reg;
}

// ---------------- pack adj (binary float) -> bitmask ---------------------
__global__ void pack_adj_kernel(const float* __restrict__ adj) {
    int idx = blockIdx.x * blockDim.x + threadIdx.x;   // 8000 * 250
    if (idx >= P_GENES * 250) return;
    int row = idx / 250, cb = idx % 250;
    const float4* p = (const float4*)(adj + (size_t)row * P_GENES + cb * 32);
    unsigned w = 0;
    #pragma unroll
    for (int q = 0; q < 8; q++) {
        float4 v = __ldcs(p + q);
        int base = q * 4;
        w |= (v.x > 0.5f ? 1u : 0u) << (base + 0);
        w |= (v.y > 0.5f ? 1u : 0u) << (base + 1);
        w |= (v.z > 0.5f ? 1u : 0u) << (base + 2);
        w |= (v.w > 0.5f ? 1u : 0u) << (base + 3);
    }
    g_adjbits[row * ABITS_ROWU32 + cb] = w;
}

// ---------------- et ----------------
__global__ void et_kernel(const float* __restrict__ eta) {
    int idx = blockIdx.x * blockDim.x + threadIdx.x;
    if (idx >= L_FAC * L_FAC) return;
    int i = idx / L_FAC, j = idx % L_FAC;
    g_et[idx] = 0.5f * (sigmoidf_(eta[i * L_FAC + j]) + sigmoidf_(eta[j * L_FAC + i]));
}

// ---------------- a = exp(alpha) -> fragment-major A-layout --------------
__global__ void expa_kernel(const float* __restrict__ alpha) {
    int idx = blockIdx.x * blockDim.x + threadIdx.x;
    if (idx >= N_PADR * 56) return;
    int row = idx / 56, kk = (idx % 56) * 2;
    float e0 = 0.0f, e1 = 0.0f;
    if (row < N_CELLS) {
        if (kk < L_FAC)     e0 = expf(alpha[row * L_FAC + kk]);
        if (kk + 1 < L_FAC) e1 = expf(alpha[row * L_FAC + kk + 1]);
    }
    g_a_fr[a_off(row, kk)] = pack_bf2(e0, e1);
}

// ---------------- per-gene: softmax, theta_, B = th@et -------------------
__global__ void __launch_bounds__(256)
theta_kernel(const float* __restrict__ theta, const float* __restrict__ gs) {
    __shared__ float et_s[L_FAC * L_FAC];
    __shared__ float th_s[16][L_FAC];
    __shared__ float gsc_s[16];

    int tid = threadIdx.x;
    for (int i = tid; i < L_FAC * L_FAC; i += 256) et_s[i] = g_et[i];

    int warp = tid >> 5, lane = tid & 31;
    int rowl = warp * 2 + (lane >> 4);
    int l16  = lane & 15;
    int gene = blockIdx.x * 16 + rowl;

    float v[7];
    float mx = -1e30f;
    #pragma unroll
    for (int j = 0; j < 7; j++) {
        int idx = l16 + 16 * j;
        v[j] = (idx < L_FAC) ? theta[gene * L_FAC + idx] : -1e30f;
        mx = fmaxf(mx, v[j]);
    }
    #pragma unroll
    for (int off = 8; off > 0; off >>= 1)
        mx = fmaxf(mx, __shfl_xor_sync(0xffffffff, mx, off, 16));
    float sum = 0.0f;
    #pragma unroll
    for (int j = 0; j < 7; j++) {
        int idx = l16 + 16 * j;
        v[j] = (idx < L_FAC) ? expf(v[j] - mx) : 0.0f;
        sum += v[j];
    }
    #pragma unroll
    for (int off = 8; off > 0; off >>= 1)
        sum += __shfl_xor_sync(0xffffffff, sum, off, 16);
    float inv = 1.0f / sum;

    #pragma unroll
    for (int j = 0; j < 7; j++) {
        int idx = l16 + 16 * j;
        if (idx < L_FAC) th_s[rowl][idx] = v[j] * inv;
    }
    if (l16 == 0) gsc_s[rowl] = sigmoidf_(gs[gene]) + DELTA_F;
    __syncthreads();

    for (int idx = tid; idx < 16 * 56; idx += 256) {
        int r = idx / 56, kk = (idx % 56) * 2;
        int n = blockIdx.x * 16 + r;
        float t0 = (kk < L_FAC) ? th_s[r][kk] : 0.0f;
        float t1 = (kk + 1 < L_FAC) ? th_s[r][kk + 1] : 0.0f;
        float g = gsc_s[r];
        int off = b_off(n, kk);
        g_th_fr [off] = pack_bf2(t0, t1);
        g_thp_fr[off] = pack_bf2(t0 * g, t1 * g);
    }

    for (int idx = tid; idx < 16 * 56; idx += 256) {
        int r = idx / 56, kk = (idx % 56) * 2;
        int row = blockIdx.x * 16 + r;
        float a0 = 0.0f, a1 = 0.0f;
        if (kk < L_FAC) {
            #pragma unroll 4
            for (int m = 0; m < L_FAC; m++) {
                float t = th_s[r][m];
                a0 = fmaf(t, et_s[m * L_FAC + kk], a0);
                if (kk + 1 < L_FAC) a1 = fmaf(t, et_s[m * L_FAC + kk + 1], a1);
            }
        }
        g_B_fr[a_off(row, kk)] = pack_bf2(a0, a1);
    }
}

// =====================================================================
// multi-tile GEMM machinery
// =====================================================================
__device__ __forceinline__ void mma16816(float c[4], const unsigned a[4],
                                         unsigned b0, unsigned b1) {
    asm volatile(
        "mma.sync.aligned.m16n8k16.row.col.f32.bf16.bf16.f32 "
        "{%0,%1,%2,%3}, {%4,%5,%6,%7}, {%8,%9}, {%0,%1,%2,%3};"
        : "+f"(c[0]), "+f"(c[1]), "+f"(c[2]), "+f"(c[3])
        : "r"(a[0]), "r"(a[1]), "r"(a[2]), "r"(a[3]), "r"(b0), "r"(b1));
}

__device__ __forceinline__ void stage_panel(char* dst, const uint4* src, int tid) {
    #pragma unroll
    for (int j = 0; j < 4; j++) {
        int i = tid + j * 512;
        if (i < PANEL_UINT4) cp16(dst + i * 16, src + i);
    }
}

// stage 128 rows x 16 bytes of adj bits for (rowBase, colPanel)
__device__ __forceinline__ void stage_bits(char* dst, int rowBase, int colPanel, int tid) {
    if (tid < 128) {
        const char* src = (const char*)g_adjbits
                        + (size_t)(rowBase + tid) * (ABITS_ROWU32 * 4) + colPanel * 16;
        cp16(dst + tid * 16, src);
    }
}

__device__ __forceinline__ void tile_mma(const char* As, const char* Bs,
                                         float acc[2][4][4], int lane, int wm, int wn) {
    int laneOff = lane * 16;
    #pragma unroll
    for (int mi = 0; mi < 2; mi++)
        #pragma unroll
        for (int nj = 0; nj < 4; nj++)
            #pragma unroll
            for (int q = 0; q < 4; q++) acc[mi][nj][q] = 0.0f;
    #pragma unroll
    for (int ks = 0; ks < 7; ks++) {
        uint4 vA0 = *(const uint4*)(As + ((2 * wm + 0) * 7 + ks) * 512 + laneOff);
        uint4 vA1 = *(const uint4*)(As + ((2 * wm + 1) * 7 + ks) * 512 + laneOff);
        uint4 vB0 = *(const uint4*)(Bs + ((2 * wn + 0) * 7 + ks) * 512 + laneOff);
        uint4 vB1 = *(const uint4*)(Bs + ((2 * wn + 1) * 7 + ks) * 512 + laneOff);
        unsigned a0[4] = {vA0.x, vA0.y, vA0.z, vA0.w};
        unsigned a1[4] = {vA1.x, vA1.y, vA1.z, vA1.w};
        mma16816(acc[0][0], a0, vB0.x, vB0.y);
        mma16816(acc[0][1], a0, vB0.z, vB0.w);
        mma16816(acc[0][2], a0, vB1.x, vB1.y);
        mma16816(acc[0][3], a0, vB1.z, vB1.w);
        mma16816(acc[1][0], a1, vB0.x, vB0.y);
        mma16816(acc[1][1], a1, vB0.z, vB0.w);
        mma16816(acc[1][2], a1, vB1.x, vB1.y);
        mma16816(acc[1][3], a1, vB1.z, vB1.w);
    }
}

__device__ __forceinline__ double block_reduce512(float lsum, int tid) {
    __shared__ float red[16];
    #pragma unroll
    for (int off = 16; off > 0; off >>= 1)
        lsum += __shfl_xor_sync(0xffffffff, lsum, off);
    if ((tid & 31) == 0) red[tid >> 5] = lsum;
    __syncthreads();
    double t = 0.0;
    if (tid == 0) {
        #pragma unroll
        for (int w = 0; w < 16; w++) t += (double)red[w];
    }
    return t;
}

// ---- recon: 7 tiles per block (R11 ordering: epilogue BEFORE wait) ----
__global__ void __launch_bounds__(512, 2)
recon_kernel(const float* __restrict__ X) {
    extern __shared__ char dsm[];
    char* As  = dsm;
    char* Bs0 = dsm + PANEL_BYTES;
    char* Bs1 = dsm + 2 * PANEL_BYTES;

    int tid = threadIdx.x;
    int lane = tid & 31, warp = tid >> 5;
    int wm = warp >> 2, wn = warp & 3;
    int rq = lane >> 2, kp = (lane & 3) << 1;
    int rowBase = blockIdx.y * 128;
    int col0 = blockIdx.x * NT;

    stage_panel(As,  ((const uint4*)g_a_fr)   + (size_t)blockIdx.y * PANEL_UINT4, tid);
    stage_panel(Bs0, ((const uint4*)g_thp_fr) + (size_t)col0 * PANEL_UINT4, tid);
    CP_COMMIT();
    CP_WAIT0();
    __syncthreads();

    float tot = 0.0f;
    #pragma unroll
    for (int t = 0; t < NT; t++) {
        char* Bcur = (t & 1) ? Bs1 : Bs0;
        char* Bnxt = (t & 1) ? Bs0 : Bs1;
        if (t + 1 < NT) {
            stage_panel(Bnxt, ((const uint4*)g_thp_fr) + (size_t)(col0 + t + 1) * PANEL_UINT4, tid);
            CP_COMMIT();
        }
        int colBase = (col0 + t) * 128;

        if ((lane & 3) == 0) {
            #pragma unroll
            for (int mi = 0; mi < 2; mi++)
                #pragma unroll
                for (int half = 0; half < 2; half++) {
                    int r = rowBase + wm * 32 + mi * 16 + rq + half * 8;
                    if (r < N_CELLS) {
                        #pragma unroll
                        for (int nj = 0; nj < 4; nj++) {
                            int c = colBase + wn * 32 + nj * 8;
                            if (c < P_GENES) pref_l2(X + (size_t)r * P_GENES + c);
                        }
                    }
                }
        }

        float acc[2][4][4];
        tile_mma(As, Bcur, acc, lane, wm, wn);

        float ls0 = 0.0f, ls1 = 0.0f;
        #pragma unroll
        for (int mi = 0; mi < 2; mi++) {
            #pragma unroll
            for (int nj = 0; nj < 4; nj++) {
                int r = rowBase + wm * 32 + mi * 16 + rq;
                int c = colBase + wn * 32 + nj * 8 + kp;
                if (c < P_GENES) {
                    if (r < N_CELLS) {
                        float2 x = *(const float2*)(X + (size_t)r * P_GENES + c);
                        float rec = acc[mi][nj][0];
                        ls0 += ((x.x > 0.0f) ? x.x * __logf(rec) : 0.0f) - rec;
                        rec = acc[mi][nj][1];
                        ls1 += ((x.y > 0.0f) ? x.y * __logf(rec) : 0.0f) - rec;
                    }
                    if (r + 8 < N_CELLS) {
                        float2 x = *(const float2*)(X + (size_t)(r + 8) * P_GENES + c);
                        float rec = acc[mi][nj][2];
                        ls0 += ((x.x > 0.0f) ? x.x * __logf(rec) : 0.0f) - rec;
                        rec = acc[mi][nj][3];
                        ls1 += ((x.y > 0.0f) ? x.y * __logf(rec) : 0.0f) - rec;
                    }
                }
            }
        }
        tot += ls0 + ls1;

        if (t + 1 < NT) {
            CP_WAIT0();
            __syncthreads();
        }
    }
    double r = block_reduce512(tot, tid);
    if (tid == 0) g_part1[blockIdx.y * NGRP + blockIdx.x] = r;
}

// ---- mat: 7 tiles per block, adj bits, grouped-log epilogue ----
__global__ void __launch_bounds__(512, 2)
mat_kernel(const float* __restrict__ kappa,
           const float* __restrict__ rho) {
    extern __shared__ char dsm[];
    char* As    = dsm;
    char* Bs0   = dsm + PANEL_BYTES;
    char* bits0 = Bs0 + PANEL_BYTES;
    char* Bs1   = bits0 + BITS_BYTES;
    char* bits1 = Bs1 + PANEL_BYTES;

    int tid = threadIdx.x;
    int lane = tid & 31, warp = tid >> 5;
    int wm = warp >> 2, wn = warp & 3;
    int rq = lane >> 2, kp = (lane & 3) << 1;
    int rowBase = blockIdx.y * 128;
    int col0 = blockIdx.x * NT;

    stage_panel(As,  ((const uint4*)g_B_fr)  + (size_t)blockIdx.y * PANEL_UINT4, tid);
    stage_panel(Bs0, ((const uint4*)g_th_fr) + (size_t)col0 * PANEL_UINT4, tid);
    stage_bits(bits0, rowBase, col0, tid);
    CP_COMMIT();
    CP_WAIT0();
    __syncthreads();

    float sk = sigmoidf_(kappa[0]);
    float sr = sigmoidf_(rho[0]);
    float Af = (1.0f - sr) * (1.0f - sk);
    float C2 = (1.0f - sr) * sk;
    float C3 = Af + sr;

    float tot = 0.0f;
    #pragma unroll
    for (int t = 0; t < NT; t++) {
        char* Bcur = (t & 1) ? Bs1 : Bs0;
        char* Bnxt = (t & 1) ? Bs0 : Bs1;
        char* bcur = (t & 1) ? bits1 : bits0;
        char* bnxt = (t & 1) ? bits0 : bits1;
        if (t + 1 < NT) {
            stage_panel(Bnxt, ((const uint4*)g_th_fr) + (size_t)(col0 + t + 1) * PANEL_UINT4, tid);
            stage_bits(bnxt, rowBase, col0 + t + 1, tid);
            CP_COMMIT();
        }
        int colBase = (col0 + t) * 128;

        float acc[2][4][4];
        tile_mma(As, Bcur, acc, lane, wm, wn);

        // adj bits: one u32 per (mi, half) row covers all 4 nj bytes
        unsigned wb[2][2];
        #pragma unroll
        for (int mi = 0; mi < 2; mi++)
            #pragma unroll
            for (int half = 0; half < 2; half++) {
                int lr = wm * 32 + mi * 16 + rq + half * 8;
                wb[mi][half] = *(const unsigned*)(bcur + lr * 16 + wn * 4);
            }

        // grouped-log epilogue: 4 running products of up to 8 factors.
        // Padding rows/cols (r >= P or c >= P) and the diagonal contribute
        // factor 1.0 exactly.
        float pr0 = 1.0f, pr1 = 1.0f, pr2 = 1.0f, pr3 = 1.0f;
        #pragma unroll
        for (int mi = 0; mi < 2; mi++) {
            #pragma unroll
            for (int nj = 0; nj < 4; nj++) {
                int r0 = rowBase + wm * 32 + mi * 16 + rq;
                int r1 = r0 + 8;
                int c  = colBase + wn * 32 + nj * 8 + kp;
                unsigned w0 = wb[mi][0] >> (nj * 8 + kp);
                unsigned w1 = wb[mi][1] >> (nj * 8 + kp);
                float m00 = acc[mi][nj][0], m01 = acc[mi][nj][1];
                float m10 = acc[mi][nj][2], m11 = acc[mi][nj][3];
                float a00 = (w0 & 1u) ? fmaf(Af, m00, C2) : fmaf(-Af, m00, C3);
                float a01 = (w0 & 2u) ? fmaf(Af, m01, C2) : fmaf(-Af, m01, C3);
                float a10 = (w1 & 1u) ? fmaf(Af, m10, C2) : fmaf(-Af, m10, C3);
                float a11 = (w1 & 2u) ? fmaf(Af, m11, C2) : fmaf(-Af, m11, C3);
                bool c0ok = (c < P_GENES), c1ok = (c + 1 < P_GENES);
                bool r0ok = (r0 < P_GENES), r1ok = (r1 < P_GENES);
                if (!r0ok || !c0ok || r0 == c)     a00 = 1.0f;
                if (!r0ok || !c1ok || r0 == c + 1) a01 = 1.0f;
                if (!r1ok || !c0ok || r1 == c)     a10 = 1.0f;
                if (!r1ok || !c1ok || r1 == c + 1) a11 = 1.0f;
                pr0 *= a00; pr1 *= a01; pr2 *= a10; pr3 *= a11;
            }
        }
        tot += (__logf(pr0) + __logf(pr1)) + (__logf(pr2) + __logf(pr3));

        if (t + 1 < NT) {
            CP_WAIT0();
            __syncthreads();
        }
    }
    double r = block_reduce512(tot, tid);
    if (tid == 0) g_part2[blockIdx.y * NGRP + blockIdx.x] = r;
}

// ---------------- final reduction ----------------
__global__ void __launch_bounds__(256)
fin_kernel(float* out) {
    int tid = threadIdx.x;
    double s1 = 0.0, s2 = 0.0;
    for (int i = tid; i < NPART1; i += 256) s1 += g_part1[i];
    for (int i = tid; i < NPART2; i += 256) s2 += g_part2[i];
    #pragma unroll
    for (int off = 16; off > 0; off >>= 1) {
        s1 += __shfl_xor_sync(0xffffffff, s1, off);
        s2 += __shfl_xor_sync(0xffffffff, s2, off);
    }
    __shared__ double r1[8], r2[8];
    if ((tid & 31) == 0) { r1[tid >> 5] = s1; r2[tid >> 5] = s2; }
    __syncthreads();
    if (tid == 0) {
        double t1 = 0.0, t2 = 0.0;
        #pragma unroll
        for (int w = 0; w < 8; w++) { t1 += r1[w]; t2 += r2[w]; }
        out[0] = (float)(-(LAM_D * t1 + t2));
    }
}

// ---------------- launch ----------------
extern "C" void kernel_launch(void* const* d_in, const int* in_sizes, int n_in,
                              void* d_out, int out_size) {
    const float* X     = (const float*)d_in[0];
    const float* adj   = (const float*)d_in[1];
    // d_in[2] adj_1m, d_in[3] weights: derivable from binary adj, unused
    const float* theta = (const float*)d_in[4];
    const float* alpha = (const float*)d_in[5];
    const float* eta   = (const float*)d_in[6];
    const float* gs    = (const float*)d_in[7];
    const float* kappa = (const float*)d_in[8];
    const float* rho   = (const float*)d_in[9];
    float* out = (float*)d_out;

    cudaFuncSetAttribute(recon_kernel, cudaFuncAttributeMaxDynamicSharedMemorySize, SMEM_RECON);
    cudaFuncSetAttribute(mat_kernel,   cudaFuncAttributeMaxDynamicSharedMemorySize, SMEM_MAT);

    // fork s2, s3 off capture stream
    cudaEventRecord(g_evStart, 0);
    cudaStreamWaitEvent(g_s2, g_evStart, 0);
    cudaStreamWaitEvent(g_s3, g_evStart, 0);

    // s3: pack adj -> bitmask (overlaps everything)
    pack_adj_kernel<<<(P_GENES * 250 + 255) / 256, 256, 0, g_s3>>>(adj);
    cudaEventRecord(g_evP, g_s3);

    // s2: a = exp(alpha)
    expa_kernel<<<(N_PADR * 56 + 255) / 256, 256, 0, g_s2>>>(alpha);
    cudaEventRecord(g_evA, g_s2);

    // s0: et -> theta
    et_kernel<<<(L_FAC * L_FAC + 255) / 256, 256>>>(eta);
    theta_kernel<<<P_GENES / 16, 256>>>(theta, gs);
    cudaEventRecord(g_evTh, 0);

    // s2: mat (needs theta outputs + adj bits)
    cudaStreamWaitEvent(g_s2, g_evTh, 0);
    cudaStreamWaitEvent(g_s2, g_evP, 0);
    dim3 gMat(NGRP, GRID_X);
    mat_kernel<<<gMat, 512, SMEM_MAT, g_s2>>>(kappa, rho);
    cudaEventRecord(g_evM, g_s2);

    // s0: recon (needs g_a and theta outputs)
    cudaStreamWaitEvent(0, g_evA, 0);
    dim3 gRecon(NGRP, GRID_Y1);
    recon_kernel<<<gRecon, 512, SMEM_RECON>>>(X);

    // join
    cudaStreamWaitEvent(0, g_evM, 0);
    fin_kernel<<<1, 256>>>(out);
}